// round 5
// baseline (speedup 1.0000x reference)
#include <cuda_runtime.h>
#include <math.h>

#define NTOK 16384
#define DDIM 2048
#define NEXP 64
#define TOPK 8

// output layout (floats)
#define OFF_TOP   0            // 16384*8
#define OFF_SC    131072       // 16384*64
#define OFF_IDX   1179648      // 16384*8
#define OFF_HIST  1310720      // 64
#define OFF_ENT   1310784      // 1

#define BM 64
#define BK 16
#define SSTR 68                 // padded row stride (floats), 16B-aligned
#define NT (DDIM / BK)          // 128 k-tiles

typedef unsigned long long u64;

__device__ __forceinline__ u64 dup2(float v) {
    u64 r; asm("mov.b64 %0, {%1, %1};" : "=l"(r) : "f"(v)); return r;
}
__device__ __forceinline__ void ffma2(u64& d, u64 a, u64 b) {
    asm("fma.rn.f32x2 %0, %1, %2, %0;" : "+l"(d) : "l"(a), "l"(b));
}

union F4U { float4 f; u64 u[2]; };
union U64F2 { u64 u; float2 f; };

__global__ void zero_tail_kernel(float* out) {
    int i = threadIdx.x;
    if (i < 65) out[OFF_HIST + i] = 0.0f;
}

__global__ __launch_bounds__(128, 4)
void router_kernel(const float* __restrict__ x,
                   const float* __restrict__ W,
                   const float* __restrict__ bias,
                   float* __restrict__ out)
{
    __shared__ float As[2][BK][SSTR];   // [buf][k][m]
    __shared__ float Bs[2][BK][SSTR];   // [buf][k][n]
    __shared__ float Sc[64 * 65];       // scores tile [m][e]
    __shared__ float sbias[64];
    __shared__ float shist[64];

    const int tid = threadIdx.x;
    const int tm4 = (tid & 15) * 4;     // 4 consecutive m per thread
    const int n0  = (tid >> 4) * 8;     // 8 consecutive n per thread
    const int m0  = blockIdx.x * BM;

    if (tid < 64) { sbias[tid] = bias[tid]; shist[tid] = 0.0f; }

    // accumulators: acc[p][j] = f32x2 over m-pair (tm4+2p, tm4+2p+1), n = n0+j
    u64 acc[2][8];
#pragma unroll
    for (int p = 0; p < 2; p++)
#pragma unroll
        for (int j = 0; j < 8; j++) acc[p][j] = 0ULL;

    // staging loads: each thread fetches 8 x-floats and 8 W-floats per tile
    const int lrow = tid >> 1;          // 0..63
    const int lk   = (tid & 1) * 8;     // 0 or 8
    const float* xp = x + (size_t)(m0 + lrow) * DDIM + lk;
    const float* wp = W + (size_t)lrow * DDIM + lk;

    float4 xa = *(const float4*)(xp);
    float4 xb = *(const float4*)(xp + 4);
    float4 wa = *(const float4*)(wp);
    float4 wb = *(const float4*)(wp + 4);

    for (int t = 0; t < NT; t++) {
        const int buf = t & 1;
        // store staged tile (transposed to [k][m] / [k][n])
        As[buf][lk + 0][lrow] = xa.x;  As[buf][lk + 1][lrow] = xa.y;
        As[buf][lk + 2][lrow] = xa.z;  As[buf][lk + 3][lrow] = xa.w;
        As[buf][lk + 4][lrow] = xb.x;  As[buf][lk + 5][lrow] = xb.y;
        As[buf][lk + 6][lrow] = xb.z;  As[buf][lk + 7][lrow] = xb.w;
        Bs[buf][lk + 0][lrow] = wa.x;  Bs[buf][lk + 1][lrow] = wa.y;
        Bs[buf][lk + 2][lrow] = wa.z;  Bs[buf][lk + 3][lrow] = wa.w;
        Bs[buf][lk + 4][lrow] = wb.x;  Bs[buf][lk + 5][lrow] = wb.y;
        Bs[buf][lk + 6][lrow] = wb.z;  Bs[buf][lk + 7][lrow] = wb.w;
        __syncthreads();

        if (t + 1 < NT) {               // prefetch next tile into registers
            xp += BK; wp += BK;
            xa = *(const float4*)(xp);
            xb = *(const float4*)(xp + 4);
            wa = *(const float4*)(wp);
            wb = *(const float4*)(wp + 4);
        }

#pragma unroll
        for (int kk = 0; kk < BK; kk++) {
            F4U a;  a.f  = *(const float4*)&As[buf][kk][tm4];   // 2 m-pairs, packed
            float4 b0 = *(const float4*)&Bs[buf][kk][n0];
            float4 b1 = *(const float4*)&Bs[buf][kk][n0 + 4];
            u64 bd[8];
            bd[0] = dup2(b0.x); bd[1] = dup2(b0.y); bd[2] = dup2(b0.z); bd[3] = dup2(b0.w);
            bd[4] = dup2(b1.x); bd[5] = dup2(b1.y); bd[6] = dup2(b1.z); bd[7] = dup2(b1.w);
#pragma unroll
            for (int j = 0; j < 8; j++) {
                ffma2(acc[0][j], a.u[0], bd[j]);
                ffma2(acc[1][j], a.u[1], bd[j]);
            }
        }
        // single sync per iter: next STS targets the other buffer; the sync
        // after that STS orders it against this iteration's reads.
    }
    __syncthreads();

    // sigmoid -> smem tile + global scores
    float* scores_out = out + OFF_SC;
#pragma unroll
    for (int p = 0; p < 2; p++) {
#pragma unroll
        for (int h = 0; h < 2; h++) {
            const int m = tm4 + 2 * p + h;
            float r[8];
#pragma unroll
            for (int j = 0; j < 8; j++) {
                U64F2 v; v.u = acc[p][j];
                float lg = h ? v.f.y : v.f.x;
                r[j] = 1.0f / (1.0f + expf(-lg));
                Sc[m * 65 + n0 + j] = r[j];
            }
            float4 o0 = make_float4(r[0], r[1], r[2], r[3]);
            float4 o1 = make_float4(r[4], r[5], r[6], r[7]);
            *(float4*)&scores_out[(size_t)(m0 + m) * NEXP + n0]     = o0;
            *(float4*)&scores_out[(size_t)(m0 + m) * NEXP + n0 + 4] = o1;
        }
    }
    __syncthreads();

    // per-token top-8 (threads 0..63), strict > scan => lowest index wins ties
    if (tid < 64) {
        const int tok = m0 + tid;
        const float* row = &Sc[tid * 65];
        unsigned long long used = 0ULL;
        float ps[TOPK];
        int   pidx[TOPK];
        float ssum = 0.0f;
#pragma unroll
        for (int k = 0; k < TOPK; k++) {
            float best = -INFINITY;
            int bi = 0;
            for (int e = 0; e < NEXP; e++) {
                if ((used >> e) & 1ULL) continue;
                float v = row[e] + sbias[e];
                if (v > best) { best = v; bi = e; }
            }
            used |= (1ULL << bi);
            float s = row[bi];
            ps[k] = s; pidx[k] = bi; ssum += s;
            atomicAdd(&shist[bi], 1.0f);
        }
        float inv = 1.0f / (ssum + 1e-20f);
        float ent = 0.0f;
#pragma unroll
        for (int k = 0; k < TOPK; k++) {
            float p = ps[k] * inv;                    // ROUTE_SCALE == 1.0
            out[OFF_TOP + (size_t)tok * TOPK + k] = p;
            out[OFF_IDX + (size_t)tok * TOPK + k] = (float)pidx[k];
            ent += p * logf(p);
        }
        atomicAdd(&out[OFF_ENT], -ent * (1.0f / (float)NTOK));
    }
    __syncthreads();
    if (tid < 64) {
        float h = shist[tid];
        if (h != 0.0f) atomicAdd(&out[OFF_HIST + tid], h);
    }
}

extern "C" void kernel_launch(void* const* d_in, const int* in_sizes, int n_in,
                              void* d_out, int out_size) {
    const float* x    = (const float*)d_in[0];
    const float* W    = (const float*)d_in[1];
    const float* bias = (const float*)d_in[2];
    float* out = (float*)d_out;

    zero_tail_kernel<<<1, 96>>>(out);
    router_kernel<<<NTOK / BM, 128>>>(x, W, bias, out);
}